// round 4
// baseline (speedup 1.0000x reference)
#include <cuda_runtime.h>
#include <math.h>
#include <float.h>

// Problem constants (fixed shapes per reference)
#define NN   32
#define CC   512
#define TT   1024
#define NT   32768      // NN*TT rows of x_flat
#define NB   2048       // codebook entries
#define CTS  524288     // CC*TT

static constexpr float MUF = 0.99f;
static constexpr float OMM = (float)(1.0 - 0.99);   // matches jax (1.0 - MU) -> f32

// Output layout: tuple concatenated in return order, all fp32
#define OUT_XD    0
#define OUT_LOSS  16777216
#define OUT_PLX   16777217
#define OUT_CB    16777218
#define OUT_SEMA  (16777218 + 1048576)   // 17825794
#define OUT_CEMA  (17825794 + 1048576)   // 18874370

// Scratch (static device globals — no allocation)
__device__ float  g_new_sum[NB * CC];
__device__ float  g_new_cnt[NB];
__device__ int    g_idx[NT];
__device__ float  g_c2[NB];
__device__ double g_loss;
__device__ float  g_plx;

// ---------------------------------------------------------------------------
__global__ void zero_kernel() {
    int i = blockIdx.x * blockDim.x + threadIdx.x;
    if (i < NB * CC) g_new_sum[i] = 0.f;
    if (i < NB)      g_new_cnt[i] = 0.f;
    if (i == 0) { g_loss = 0.0; g_plx = 0.f; }
}

// ---------------------------------------------------------------------------
// c2[k] = sum_c codebook[k][c]^2  (one warp per code)
__global__ void c2_kernel(const float* __restrict__ cb) {
    int gw = (blockIdx.x * blockDim.x + threadIdx.x) >> 5;
    int lane = threadIdx.x & 31;
    if (gw >= NB) return;
    const float* row = cb + (size_t)gw * CC;
    float s = 0.f;
    #pragma unroll 4
    for (int c = lane; c < CC; c += 32) { float v = row[c]; s += v * v; }
    #pragma unroll
    for (int o = 16; o; o >>= 1) s += __shfl_xor_sync(0xffffffffu, s, o);
    if (lane == 0) g_c2[gw] = s;
}

// ---------------------------------------------------------------------------
// Fused distance GEMM + argmin.
// Block: 64 rows (consecutive t within one n) x all 2048 codes (chunks of 128).
// 256 threads, 4x8 microtile, BK=16.
__global__ __launch_bounds__(256) void argmin_kernel(const float* __restrict__ x,
                                                     const float* __restrict__ cb) {
    __shared__ float As[16][68];    // [k][row], padded
    __shared__ float Bs[16][132];   // [k][code], padded (float4-aligned rows)

    const int tid = threadIdx.x;
    const int tx = tid & 15;        // code group
    const int ty = tid >> 4;        // row group
    const int row0 = blockIdx.x * 64;
    const int n = row0 / TT;
    const int t0 = row0 % TT;
    const float* xb = x + (size_t)n * CTS + t0;

    float bestd[4];
    int   besti[4];
    #pragma unroll
    for (int i = 0; i < 4; i++) { bestd[i] = FLT_MAX; besti[i] = 0; }

    const int lr = tid & 63;        // As: row within tile
    const int lk = tid >> 6;        // As: k base (0..3)
    const int bch = tid & 15;       // Bs: channel within k-tile
    const int bcd = tid >> 4;       // Bs: code base (0..15)

    for (int cc = 0; cc < NB; cc += 128) {
        float acc[4][8];
        #pragma unroll
        for (int i = 0; i < 4; i++)
            #pragma unroll
            for (int j = 0; j < 8; j++) acc[i][j] = 0.f;

        for (int kt = 0; kt < CC; kt += 16) {
            #pragma unroll
            for (int l = 0; l < 4; l++)
                As[lk + l * 4][lr] = xb[(size_t)(kt + lk + l * 4) * TT + lr];
            #pragma unroll
            for (int l = 0; l < 8; l++)
                Bs[bch][bcd + l * 16] = cb[(size_t)(cc + bcd + l * 16) * CC + kt + bch];
            __syncthreads();

            #pragma unroll
            for (int k = 0; k < 16; k++) {
                float4 a  = *(const float4*)&As[k][ty * 4];
                float4 b0 = *(const float4*)&Bs[k][tx * 4];
                float4 b1 = *(const float4*)&Bs[k][tx * 4 + 64];
                float av[4] = {a.x, a.y, a.z, a.w};
                float bv[8] = {b0.x, b0.y, b0.z, b0.w, b1.x, b1.y, b1.z, b1.w};
                #pragma unroll
                for (int i = 0; i < 4; i++)
                    #pragma unroll
                    for (int j = 0; j < 8; j++)
                        acc[i][j] = fmaf(av[i], bv[j], acc[i][j]);
            }
            __syncthreads();
        }

        // distances for this code chunk: d = c2 - 2*dot  (x^2 constant per row)
        #pragma unroll
        for (int j = 0; j < 8; j++) {
            int c = (j < 4) ? (tx * 4 + j) : (64 + tx * 4 + (j - 4));
            int gc = cc + c;
            float c2v = g_c2[gc];
            #pragma unroll
            for (int i = 0; i < 4; i++) {
                float d = c2v - 2.f * acc[i][j];
                if (d < bestd[i]) { bestd[i] = d; besti[i] = gc; }
            }
        }
    }

    // reduce across the 16 tx lanes sharing each row (first-occurrence tie-break)
    #pragma unroll
    for (int i = 0; i < 4; i++) {
        float d = bestd[i];
        int bi = besti[i];
        #pragma unroll
        for (int off = 8; off; off >>= 1) {
            float od = __shfl_xor_sync(0xffffffffu, d, off);
            int   oi = __shfl_xor_sync(0xffffffffu, bi, off);
            if (od < d || (od == d && oi < bi)) { d = od; bi = oi; }
        }
        if (tx == 0) g_idx[row0 + ty * 4 + i] = bi;
    }
}

// ---------------------------------------------------------------------------
// Gather codebook rows -> x_d_out (transposed back to (N,C,T)), segment sums,
// commit-loss accumulation.  Block = (n, 32 consecutive t), 256 threads.
__global__ __launch_bounds__(256) void scatter_kernel(const float* __restrict__ x,
                                                      const float* __restrict__ cb,
                                                      float* __restrict__ out) {
    __shared__ int   sidx[32];
    __shared__ float tile[32][33];
    __shared__ float red[8];

    const int b = blockIdx.x;
    const int n = b >> 5;
    const int t0 = (b & 31) * 32;
    const int tid = threadIdx.x;
    const int w = tid >> 5;
    const int lane = tid & 31;

    if (tid < 32) sidx[tid] = g_idx[n * TT + t0 + tid];
    __syncthreads();
    if (tid < 32) atomicAdd(&g_new_cnt[sidx[tid]], 1.0f);

    float lsum = 0.f;
    for (int c0 = 0; c0 < CC; c0 += 32) {
        #pragma unroll
        for (int i = 0; i < 4; i++) {
            int t = w * 4 + i;
            tile[t][lane] = cb[(size_t)sidx[t] * CC + c0 + lane];
        }
        __syncthreads();
        #pragma unroll
        for (int i = 0; i < 4; i++) {
            int cr = w * 4 + i;
            int c = c0 + cr;
            size_t off = (size_t)n * CTS + (size_t)c * TT + t0 + lane;
            float xv = x[off];
            float v = tile[lane][cr];
            out[OUT_XD + off] = v;
            float dd = xv - v;
            lsum += dd * dd;
            atomicAdd(&g_new_sum[(size_t)sidx[lane] * CC + c], xv);
        }
        __syncthreads();
    }

    #pragma unroll
    for (int o = 16; o; o >>= 1) lsum += __shfl_xor_sync(0xffffffffu, lsum, o);
    if (lane == 0) red[w] = lsum;
    __syncthreads();
    if (tid == 0) {
        float s = 0.f;
        #pragma unroll
        for (int i = 0; i < 8; i++) s += red[i];
        atomicAdd(&g_loss, (double)s);
    }
}

// ---------------------------------------------------------------------------
// EMA updates, codebook reset, perplexity partials. One block per code.
__global__ __launch_bounds__(128) void finalize_kernel(const float* __restrict__ x,
                                                       const float* __restrict__ code_sum,
                                                       const float* __restrict__ code_count,
                                                       float* __restrict__ out) {
    const int k = blockIdx.x;
    const int tid = threadIdx.x;
    float ncnt = g_new_cnt[k];
    float cnt_ema = MUF * code_count[k] + OMM * ncnt;
    bool usage = (cnt_ema >= 1.0f);
    float denom = fmaxf(cnt_ema, 1e-10f);

    for (int c = tid; c < CC; c += 128) {
        float sema = MUF * code_sum[(size_t)k * CC + c] + OMM * g_new_sum[(size_t)k * CC + c];
        out[OUT_SEMA + (size_t)k * CC + c] = sema;
        float v;
        if (usage) v = sema / denom;
        else       v = x[(size_t)(k >> 10) * CTS + (size_t)c * TT + (k & 1023)];
        out[OUT_CB + (size_t)k * CC + c] = v;
    }
    if (tid == 0) {
        out[OUT_CEMA + k] = cnt_ema;
        float p = ncnt / 32768.0f;           // sum(new_count) == 32768 exactly in f32
        atomicAdd(&g_plx, p * logf(p + 1e-7f));
    }
}

// ---------------------------------------------------------------------------
__global__ void scalars_kernel(float* __restrict__ out) {
    out[OUT_LOSS] = (float)(g_loss * (1.0 / 16777216.0));
    out[OUT_PLX] = expf(-g_plx);
}

// ---------------------------------------------------------------------------
extern "C" void kernel_launch(void* const* d_in, const int* in_sizes, int n_in,
                              void* d_out, int out_size) {
    const float* x    = (const float*)d_in[0];
    const float* cb   = (const float*)d_in[1];
    const float* csum = (const float*)d_in[2];
    const float* ccnt = (const float*)d_in[3];
    float* out = (float*)d_out;

    zero_kernel<<<(NB * CC + 255) / 256, 256>>>();
    c2_kernel<<<(NB * 32 + 255) / 256, 256>>>(cb);
    argmin_kernel<<<NT / 64, 256>>>(x, cb);
    scatter_kernel<<<NN * (TT / 32), 256>>>(x, cb, out);
    finalize_kernel<<<NB, 128>>>(x, csum, ccnt, out);
    scalars_kernel<<<1, 1>>>(out);
}

// round 7
// speedup vs baseline: 1.7171x; 1.7171x over previous
#include <cuda_runtime.h>
#include <cuda_bf16.h>
#include <math.h>
#include <float.h>
#include <stdint.h>

// Problem constants (fixed shapes per reference)
#define NN   32
#define CC   512
#define TT   1024
#define NT   32768      // NN*TT rows of x_flat
#define NB   2048       // codebook entries
#define CTS  524288     // CC*TT

static constexpr float MUF = 0.99f;
static constexpr float OMM = (float)(1.0 - 0.99);

// Output layout: tuple concatenated in return order, all fp32
#define OUT_XD    0
#define OUT_LOSS  16777216
#define OUT_PLX   16777217
#define OUT_CB    16777218
#define OUT_SEMA  (16777218 + 1048576)
#define OUT_CEMA  (17825794 + 1048576)

// Scratch (static device globals — no allocation)
__device__ float  g_new_sum[NB * CC];
__device__ float  g_new_cnt[NB];
__device__ int    g_idx[NT];
__device__ float  g_c2[NB];
__device__ double g_loss;
__device__ float  g_plx;

__device__ __align__(16) __nv_bfloat16 g_xhi[(size_t)NT * CC];
__device__ __align__(16) __nv_bfloat16 g_xlo[(size_t)NT * CC];
__device__ __align__(16) __nv_bfloat16 g_cbhi[(size_t)NB * CC];
__device__ __align__(16) __nv_bfloat16 g_cblo[(size_t)NB * CC];
__device__ int g_resc_cnt;
__device__ int g_resc_row[NT];
__device__ int g_resc_i1[NT];
__device__ int g_resc_i2[NT];

// ===========================================================================
__device__ __forceinline__ uint32_t smem_to_u32(const void* p) {
    uint32_t a;
    asm("{ .reg .u64 t; cvta.to.shared.u64 t, %1; cvt.u32.u64 %0, t; }" : "=r"(a) : "l"(p));
    return a;
}
__device__ __forceinline__ void cp16(uint32_t dst, const void* src) {
    asm volatile("cp.async.cg.shared.global [%0], [%1], 16;" :: "r"(dst), "l"(src));
}
__device__ __forceinline__ void mma16816(float* c, const uint32_t* a, uint32_t b0, uint32_t b1) {
    asm volatile(
        "mma.sync.aligned.m16n8k16.row.col.f32.bf16.bf16.f32 "
        "{%0,%1,%2,%3}, {%4,%5,%6,%7}, {%8,%9}, {%0,%1,%2,%3};"
        : "+f"(c[0]), "+f"(c[1]), "+f"(c[2]), "+f"(c[3])
        : "r"(a[0]), "r"(a[1]), "r"(a[2]), "r"(a[3]), "r"(b0), "r"(b1));
}

// ===========================================================================
// Trivial prologue kernels
// ===========================================================================
__global__ void zero_kernel() {
    int i = blockIdx.x * blockDim.x + threadIdx.x;
    if (i < NB * CC) g_new_sum[i] = 0.f;
    if (i < NB)      g_new_cnt[i] = 0.f;
    if (i == 0) { g_loss = 0.0; g_plx = 0.f; g_resc_cnt = 0; }
}

__global__ void c2_kernel(const float* __restrict__ cb) {
    int gw = (blockIdx.x * blockDim.x + threadIdx.x) >> 5;
    int lane = threadIdx.x & 31;
    if (gw >= NB) return;
    const float* row = cb + (size_t)gw * CC;
    float s = 0.f;
    #pragma unroll 4
    for (int c = lane; c < CC; c += 32) { float v = row[c]; s += v * v; }
    #pragma unroll
    for (int o = 16; o; o >>= 1) s += __shfl_xor_sync(0xffffffffu, s, o);
    if (lane == 0) g_c2[gw] = s;
}

// Codebook split: cb -> bf16 hi + bf16 lo
__global__ void cvtcb_kernel(const float* __restrict__ cb) {
    int i = blockIdx.x * blockDim.x + threadIdx.x;
    if (i < NB * CC) {
        float v = cb[i];
        __nv_bfloat16 h = __float2bfloat16(v);
        g_cbhi[i] = h;
        g_cblo[i] = __float2bfloat16(v - __bfloat162float(h));
    }
}

// x split + transpose: x(N,C,T) -> row-major x_flat[row=n*T+t][c], bf16 hi/lo
__global__ __launch_bounds__(256) void cvtx_kernel(const float* __restrict__ x) {
    __shared__ float tile[32][33];
    int b = blockIdx.x;
    int n   = b >> 9;
    int rem = b & 511;
    int t0 = (rem >> 4) << 5;
    int c0 = (rem & 15) << 5;
    int w = threadIdx.x >> 5, lane = threadIdx.x & 31;
    #pragma unroll
    for (int i = 0; i < 4; i++) {
        int cl = w * 4 + i;
        tile[lane][cl] = x[(size_t)n * CTS + (size_t)(c0 + cl) * TT + t0 + lane];
    }
    __syncthreads();
    #pragma unroll
    for (int i = 0; i < 4; i++) {
        int tl = w * 4 + i;
        float v = tile[tl][lane];
        size_t o = (size_t)(n * TT + t0 + tl) * CC + c0 + lane;
        __nv_bfloat16 h = __float2bfloat16(v);
        g_xhi[o] = h;
        g_xlo[o] = __float2bfloat16(v - __bfloat162float(h));
    }
}

// ===========================================================================
// HMMA (mma.sync m16n8k16 bf16) bf16x3 distance GEMM + fused argmin
//   CTA: 128 rows x 2048 codes (16 chunks of 128); K=512 in 16 tiles of 32.
//   8 warps = 4 row-groups x 2 col-groups; warp tile 32x64.
// ===========================================================================
// smem layout (dynamic):
#define SC2_OFF   0          // 2048 f32 = 8192 B
#define MD1_OFF   8192       // 128 f32
#define MI1_OFF   8704       // 128 i32
#define MD2_OFF   9216       // 128 f32
#define MI2_OFF   9728       // 128 i32
#define STAGE0    10240
#define ROWB      80         // bytes per smem row (32 bf16 + 16B pad)
#define OFF_AH    0
#define OFF_AL    10240      // 128*80
#define OFF_BH    20480
#define OFF_BL    30720
#define STAGE_SZ  40960
#define SMEM_TOTAL_MMA (10240 + 2 * STAGE_SZ)   // 92160
#define THRESH 0.05f

__device__ __forceinline__ void load_tiles(uint32_t sb, int r0, int i) {
    const int tid = threadIdx.x;
    const int kt = i & 15;          // k-tile (32 elems)
    const int cc = i >> 4;          // code chunk (128 codes)
    const uint32_t stage = sb + STAGE0 + (uint32_t)(i & 1) * STAGE_SZ;
    const int kofs = kt << 5;
    #pragma unroll
    for (int u = 0; u < 2; u++) {
        int idx = tid + (u << 8);
        int row = idx >> 2, c16 = idx & 3;
        uint32_t off = (uint32_t)(row * ROWB + c16 * 16);
        size_t ga = (size_t)(r0 + row) * CC + kofs + (c16 << 3);
        cp16(stage + OFF_AH + off, &g_xhi[ga]);
        cp16(stage + OFF_AL + off, &g_xlo[ga]);
        size_t gb = (size_t)((cc << 7) + row) * CC + kofs + (c16 << 3);
        cp16(stage + OFF_BH + off, &g_cbhi[gb]);
        cp16(stage + OFF_BL + off, &g_cblo[gb]);
    }
}

__device__ __forceinline__ void upd2(float& d1, int& i1, float& d2, int& i2,
                                     float d, int code) {
    if (d < d1)      { d2 = d1; i2 = i1; d1 = d; i1 = code; }
    else if (d < d2) { d2 = d; i2 = code; }
}
__device__ __forceinline__ void merge2(float& d1, int& i1, float& d2, int& i2,
                                       float od1, int oi1, float od2, int oi2) {
    if (od1 < d1 || (od1 == d1 && oi1 < i1)) {
        if (d1 < od2 || (d1 == od2 && i1 < oi2)) { d2 = d1; i2 = i1; }
        else                                      { d2 = od2; i2 = oi2; }
        d1 = od1; i1 = oi1;
    } else {
        if (od1 < d2 || (od1 == d2 && oi1 < i2)) { d2 = od1; i2 = oi1; }
    }
}

__global__ __launch_bounds__(256, 1) void mma_argmin_kernel() {
    extern __shared__ char smem[];
    const uint32_t sb = smem_to_u32(smem);
    const int tid = threadIdx.x;
    const int wid = tid >> 5;
    const int lane = tid & 31;
    const int wr = (wid >> 1) * 32;     // warp row offset (0/32/64/96)
    const int wc = (wid & 1) * 64;      // warp col offset (0/64)
    const int g = lane >> 2;            // 0..7
    const int q = lane & 3;             // 0..3
    const int r0 = blockIdx.x * 128;

    float* sc2 = (float*)(smem + SC2_OFF);
    for (int c = tid; c < NB; c += 256) sc2[c] = g_c2[c];

    float acc[2][8][4];
    float bd1[4], bd2[4]; int bi1[4], bi2[4];
    #pragma unroll
    for (int s = 0; s < 4; s++) { bd1[s] = FLT_MAX; bd2[s] = FLT_MAX; bi1[s] = 0; bi2[s] = 0; }

    load_tiles(sb, r0, 0);
    asm volatile("cp.async.commit_group;" ::: "memory");

    for (int i = 0; i < 256; i++) {
        const int kt = i & 15;
        const int cc = i >> 4;
        if (i + 1 < 256) {
            load_tiles(sb, r0, i + 1);
            asm volatile("cp.async.commit_group;" ::: "memory");
            asm volatile("cp.async.wait_group 1;" ::: "memory");
        } else {
            asm volatile("cp.async.wait_group 0;" ::: "memory");
        }
        __syncthreads();

        if (kt == 0) {
            #pragma unroll
            for (int mt = 0; mt < 2; mt++)
                #pragma unroll
                for (int nt = 0; nt < 8; nt++)
                    #pragma unroll
                    for (int r = 0; r < 4; r++) acc[mt][nt][r] = 0.f;
        }

        const char* stage = smem + STAGE0 + (size_t)(i & 1) * STAGE_SZ;
        #pragma unroll
        for (int ks = 0; ks < 2; ks++) {
            const int kb = (ks * 16 + q * 2) * 2;   // byte offset within row
            uint32_t af[2][2][4];                   // [mt][hi/lo][4]
            #pragma unroll
            for (int mt = 0; mt < 2; mt++) {
                int row = wr + mt * 16 + g;
                const char* ah = stage + OFF_AH + row * ROWB + kb;
                const char* al = stage + OFF_AL + row * ROWB + kb;
                af[mt][0][0] = *(const uint32_t*)(ah);
                af[mt][0][1] = *(const uint32_t*)(ah + 8 * ROWB);
                af[mt][0][2] = *(const uint32_t*)(ah + 16);
                af[mt][0][3] = *(const uint32_t*)(ah + 8 * ROWB + 16);
                af[mt][1][0] = *(const uint32_t*)(al);
                af[mt][1][1] = *(const uint32_t*)(al + 8 * ROWB);
                af[mt][1][2] = *(const uint32_t*)(al + 16);
                af[mt][1][3] = *(const uint32_t*)(al + 8 * ROWB + 16);
            }
            #pragma unroll
            for (int nt = 0; nt < 8; nt++) {
                int n = wc + nt * 8 + g;
                const char* bh = stage + OFF_BH + n * ROWB + kb;
                const char* bl = stage + OFF_BL + n * ROWB + kb;
                uint32_t bh0 = *(const uint32_t*)(bh);
                uint32_t bh1 = *(const uint32_t*)(bh + 16);
                uint32_t bl0 = *(const uint32_t*)(bl);
                uint32_t bl1 = *(const uint32_t*)(bl + 16);
                #pragma unroll
                for (int mt = 0; mt < 2; mt++) {
                    mma16816(acc[mt][nt], af[mt][0], bh0, bh1);   // xh*ch
                    mma16816(acc[mt][nt], af[mt][0], bl0, bl1);   // xh*cl
                    mma16816(acc[mt][nt], af[mt][1], bh0, bh1);   // xl*ch
                }
            }
        }

        if (kt == 15) {
            // chunk epilogue: d = c2 - 2*dot; track best/second per row slot
            #pragma unroll
            for (int mt = 0; mt < 2; mt++) {
                #pragma unroll
                for (int nt = 0; nt < 8; nt++) {
                    int code0 = (cc << 7) + wc + nt * 8 + q * 2;
                    float c2a = sc2[code0], c2b = sc2[code0 + 1];
                    upd2(bd1[mt*2], bi1[mt*2], bd2[mt*2], bi2[mt*2],
                         c2a - 2.f * acc[mt][nt][0], code0);
                    upd2(bd1[mt*2], bi1[mt*2], bd2[mt*2], bi2[mt*2],
                         c2b - 2.f * acc[mt][nt][1], code0 + 1);
                    upd2(bd1[mt*2+1], bi1[mt*2+1], bd2[mt*2+1], bi2[mt*2+1],
                         c2a - 2.f * acc[mt][nt][2], code0);
                    upd2(bd1[mt*2+1], bi1[mt*2+1], bd2[mt*2+1], bi2[mt*2+1],
                         c2b - 2.f * acc[mt][nt][3], code0 + 1);
                }
            }
        }
        __syncthreads();
    }

    // reduce across the 4 lanes sharing each row (xor 1, 2)
    #pragma unroll
    for (int s = 0; s < 4; s++) {
        #pragma unroll
        for (int o = 1; o <= 2; o <<= 1) {
            float od1 = __shfl_xor_sync(0xffffffffu, bd1[s], o);
            int   oi1 = __shfl_xor_sync(0xffffffffu, bi1[s], o);
            float od2 = __shfl_xor_sync(0xffffffffu, bd2[s], o);
            int   oi2 = __shfl_xor_sync(0xffffffffu, bi2[s], o);
            merge2(bd1[s], bi1[s], bd2[s], bi2[s], od1, oi1, od2, oi2);
        }
    }

    float* md1 = (float*)(smem + MD1_OFF);
    int*   mi1 = (int*)  (smem + MI1_OFF);
    float* md2 = (float*)(smem + MD2_OFF);
    int*   mi2 = (int*)  (smem + MI2_OFF);

    if ((wid & 1) == 1 && q == 0) {
        #pragma unroll
        for (int s = 0; s < 4; s++) {
            int row = wr + (s >> 1) * 16 + (s & 1) * 8 + g;
            md1[row] = bd1[s]; mi1[row] = bi1[s];
            md2[row] = bd2[s]; mi2[row] = bi2[s];
        }
    }
    __syncthreads();
    if ((wid & 1) == 0 && q == 0) {
        #pragma unroll
        for (int s = 0; s < 4; s++) {
            int row = wr + (s >> 1) * 16 + (s & 1) * 8 + g;
            merge2(bd1[s], bi1[s], bd2[s], bi2[s],
                   md1[row], mi1[row], md2[row], mi2[row]);
            g_idx[r0 + row] = bi1[s];
            if (bd2[s] - bd1[s] < THRESH) {
                int pos = atomicAdd(&g_resc_cnt, 1);
                g_resc_row[pos] = r0 + row;
                g_resc_i1[pos]  = bi1[s];
                g_resc_i2[pos]  = bi2[s];
            }
        }
    }
}

// ===========================================================================
// Exact fp32 rescore of top-2 candidates for small-margin rows
// ===========================================================================
__global__ __launch_bounds__(256) void rescue_kernel(const float* __restrict__ x,
                                                     const float* __restrict__ cb) {
    const int cnt = g_resc_cnt;
    const int wid = threadIdx.x >> 5;
    const int lane = threadIdx.x & 31;
    for (int j = blockIdx.x * 8 + wid; j < cnt; j += gridDim.x * 8) {
        int row = g_resc_row[j], ia = g_resc_i1[j], ib = g_resc_i2[j];
        int n = row >> 10, t = row & 1023;
        const float* xr = x + (size_t)n * CTS + t;
        const float* ca = cb + (size_t)ia * CC;
        const float* cbp = cb + (size_t)ib * CC;
        float s1 = 0.f, s2 = 0.f;
        #pragma unroll 4
        for (int c = lane; c < CC; c += 32) {
            float xv = xr[(size_t)c * TT];
            s1 += xv * ca[c];
            s2 += xv * cbp[c];
        }
        #pragma unroll
        for (int o = 16; o; o >>= 1) {
            s1 += __shfl_xor_sync(0xffffffffu, s1, o);
            s2 += __shfl_xor_sync(0xffffffffu, s2, o);
        }
        if (lane == 0) {
            float da = g_c2[ia] - 2.f * s1;
            float db = g_c2[ib] - 2.f * s2;
            int best = (db < da || (db == da && ib < ia)) ? ib : ia;
            g_idx[row] = best;
        }
    }
}

// ===========================================================================
// Gather codebook rows -> x_d_out, segment sums, commit-loss
// ===========================================================================
__global__ __launch_bounds__(256) void scatter_kernel(const float* __restrict__ x,
                                                      const float* __restrict__ cb,
                                                      float* __restrict__ out) {
    __shared__ int   sidx[32];
    __shared__ float tile[32][33];
    __shared__ float red[8];

    const int b = blockIdx.x;
    const int n = b >> 5;
    const int t0 = (b & 31) * 32;
    const int tid = threadIdx.x;
    const int w = tid >> 5;
    const int lane = tid & 31;

    if (tid < 32) sidx[tid] = g_idx[n * TT + t0 + tid];
    __syncthreads();
    if (tid < 32) atomicAdd(&g_new_cnt[sidx[tid]], 1.0f);

    float lsum = 0.f;
    for (int c0 = 0; c0 < CC; c0 += 32) {
        #pragma unroll
        for (int i = 0; i < 4; i++) {
            int t = w * 4 + i;
            tile[t][lane] = cb[(size_t)sidx[t] * CC + c0 + lane];
        }
        __syncthreads();
        #pragma unroll
        for (int i = 0; i < 4; i++) {
            int cr = w * 4 + i;
            int c = c0 + cr;
            size_t off = (size_t)n * CTS + (size_t)c * TT + t0 + lane;
            float xv = x[off];
            float v = tile[lane][cr];
            out[OUT_XD + off] = v;
            float dd = xv - v;
            lsum += dd * dd;
            atomicAdd(&g_new_sum[(size_t)sidx[lane] * CC + c], xv);
        }
        __syncthreads();
    }

    #pragma unroll
    for (int o = 16; o; o >>= 1) lsum += __shfl_xor_sync(0xffffffffu, lsum, o);
    if (lane == 0) red[w] = lsum;
    __syncthreads();
    if (tid == 0) {
        float s = 0.f;
        #pragma unroll
        for (int i = 0; i < 8; i++) s += red[i];
        atomicAdd(&g_loss, (double)s);
    }
}

// ===========================================================================
// EMA updates, codebook reset, perplexity partials
// ===========================================================================
__global__ __launch_bounds__(128) void finalize_kernel(const float* __restrict__ x,
                                                       const float* __restrict__ code_sum,
                                                       const float* __restrict__ code_count,
                                                       float* __restrict__ out) {
    const int k = blockIdx.x;
    const int tid = threadIdx.x;
    float ncnt = g_new_cnt[k];
    float cnt_ema = MUF * code_count[k] + OMM * ncnt;
    bool usage = (cnt_ema >= 1.0f);
    float denom = fmaxf(cnt_ema, 1e-10f);

    for (int c = tid; c < CC; c += 128) {
        float sema = MUF * code_sum[(size_t)k * CC + c] + OMM * g_new_sum[(size_t)k * CC + c];
        out[OUT_SEMA + (size_t)k * CC + c] = sema;
        float v;
        if (usage) v = sema / denom;
        else       v = x[(size_t)(k >> 10) * CTS + (size_t)c * TT + (k & 1023)];
        out[OUT_CB + (size_t)k * CC + c] = v;
    }
    if (tid == 0) {
        out[OUT_CEMA + k] = cnt_ema;
        float p = ncnt / 32768.0f;
        atomicAdd(&g_plx, p * logf(p + 1e-7f));
    }
}

__global__ void scalars_kernel(float* __restrict__ out) {
    out[OUT_LOSS] = (float)(g_loss * (1.0 / 16777216.0));
    out[OUT_PLX] = expf(-g_plx);
}

// ===========================================================================
extern "C" void kernel_launch(void* const* d_in, const int* in_sizes, int n_in,
                              void* d_out, int out_size) {
    const float* x    = (const float*)d_in[0];
    const float* cb   = (const float*)d_in[1];
    const float* csum = (const float*)d_in[2];
    const float* ccnt = (const float*)d_in[3];
    float* out = (float*)d_out;

    cudaFuncSetAttribute(mma_argmin_kernel,
                         cudaFuncAttributeMaxDynamicSharedMemorySize, SMEM_TOTAL_MMA);

    zero_kernel<<<(NB * CC + 255) / 256, 256>>>();
    c2_kernel<<<(NB * 32 + 255) / 256, 256>>>(cb);
    cvtcb_kernel<<<(NB * CC + 255) / 256, 256>>>(cb);
    cvtx_kernel<<<NN * 512, 256>>>(x);
    mma_argmin_kernel<<<NT / 128, 256, SMEM_TOTAL_MMA>>>();
    rescue_kernel<<<128, 256>>>(x, cb);
    scatter_kernel<<<NN * (TT / 32), 256>>>(x, cb, out);
    finalize_kernel<<<NB, 128>>>(x, csum, ccnt, out);
    scalars_kernel<<<1, 1>>>(out);
}

// round 10
// speedup vs baseline: 2.5518x; 1.4861x over previous
#include <cuda_runtime.h>
#include <cuda_bf16.h>
#include <math.h>
#include <float.h>
#include <stdint.h>

// Problem constants (fixed shapes per reference)
#define NN   32
#define CC   512
#define TT   1024
#define NT   32768      // NN*TT rows of x_flat
#define NB   2048       // codebook entries
#define CTS  524288     // CC*TT

static constexpr float MUF = 0.99f;
static constexpr float OMM = (float)(1.0 - 0.99);

// Output layout: tuple concatenated in return order, all fp32
#define OUT_XD    0
#define OUT_LOSS  16777216
#define OUT_PLX   16777217
#define OUT_CB    16777218
#define OUT_SEMA  (16777218 + 1048576)
#define OUT_CEMA  (17825794 + 1048576)

// Scratch (static device globals — no allocation)
__device__ float  g_new_sum[NB * CC];
__device__ float  g_new_cnt[NB];
__device__ int    g_idx[NT];
__device__ float  g_c2[NB];
__device__ double g_loss;
__device__ float  g_plx;

__device__ __align__(16) __nv_bfloat16 g_xhi[(size_t)NT * CC];
__device__ __align__(16) __nv_bfloat16 g_xlo[(size_t)NT * CC];
__device__ __align__(16) __nv_bfloat16 g_cbhi[(size_t)NB * CC];
__device__ __align__(16) __nv_bfloat16 g_cblo[(size_t)NB * CC];
__device__ int g_resc_cnt;
__device__ int g_resc_row[NT];
__device__ int g_resc_i1[NT];
__device__ int g_resc_i2[NT];

// ===========================================================================
__device__ __forceinline__ uint32_t smem_to_u32(const void* p) {
    uint32_t a;
    asm("{ .reg .u64 t; cvta.to.shared.u64 t, %1; cvt.u32.u64 %0, t; }" : "=r"(a) : "l"(p));
    return a;
}
__device__ __forceinline__ void cp16(uint32_t dst, const void* src) {
    asm volatile("cp.async.cg.shared.global [%0], [%1], 16;" :: "r"(dst), "l"(src));
}
__device__ __forceinline__ void mma16816(float* c, const uint32_t* a, uint32_t b0, uint32_t b1) {
    asm volatile(
        "mma.sync.aligned.m16n8k16.row.col.f32.bf16.bf16.f32 "
        "{%0,%1,%2,%3}, {%4,%5,%6,%7}, {%8,%9}, {%0,%1,%2,%3};"
        : "+f"(c[0]), "+f"(c[1]), "+f"(c[2]), "+f"(c[3])
        : "r"(a[0]), "r"(a[1]), "r"(a[2]), "r"(a[3]), "r"(b0), "r"(b1));
}
__device__ __forceinline__ void ldsm_x4(uint32_t* r, uint32_t addr) {
    asm volatile("ldmatrix.sync.aligned.m8n8.x4.shared.b16 {%0,%1,%2,%3}, [%4];"
        : "=r"(r[0]), "=r"(r[1]), "=r"(r[2]), "=r"(r[3]) : "r"(addr));
}

// ===========================================================================
// Trivial prologue kernels
// ===========================================================================
__global__ void zero_kernel() {
    int i = blockIdx.x * blockDim.x + threadIdx.x;
    if (i < NB * CC) g_new_sum[i] = 0.f;
    if (i < NB)      g_new_cnt[i] = 0.f;
    if (i == 0) { g_loss = 0.0; g_plx = 0.f; g_resc_cnt = 0; }
}

__global__ void c2_kernel(const float* __restrict__ cb) {
    int gw = (blockIdx.x * blockDim.x + threadIdx.x) >> 5;
    int lane = threadIdx.x & 31;
    if (gw >= NB) return;
    const float* row = cb + (size_t)gw * CC;
    float s = 0.f;
    #pragma unroll 4
    for (int c = lane; c < CC; c += 32) { float v = row[c]; s += v * v; }
    #pragma unroll
    for (int o = 16; o; o >>= 1) s += __shfl_xor_sync(0xffffffffu, s, o);
    if (lane == 0) g_c2[gw] = s;
}

// Codebook split: cb -> bf16 hi + bf16 lo
__global__ void cvtcb_kernel(const float* __restrict__ cb) {
    int i = blockIdx.x * blockDim.x + threadIdx.x;
    if (i < NB * CC) {
        float v = cb[i];
        __nv_bfloat16 h = __float2bfloat16(v);
        g_cbhi[i] = h;
        g_cblo[i] = __float2bfloat16(v - __bfloat162float(h));
    }
}

// x split + transpose: x(N,C,T) -> row-major x_flat[row=n*T+t][c], bf16 hi/lo
__global__ __launch_bounds__(256) void cvtx_kernel(const float* __restrict__ x) {
    __shared__ float tile[32][33];
    int b = blockIdx.x;
    int n   = b >> 9;
    int rem = b & 511;
    int t0 = (rem >> 4) << 5;
    int c0 = (rem & 15) << 5;
    int w = threadIdx.x >> 5, lane = threadIdx.x & 31;
    #pragma unroll
    for (int i = 0; i < 4; i++) {
        int cl = w * 4 + i;
        tile[lane][cl] = x[(size_t)n * CTS + (size_t)(c0 + cl) * TT + t0 + lane];
    }
    __syncthreads();
    #pragma unroll
    for (int i = 0; i < 4; i++) {
        int tl = w * 4 + i;
        float v = tile[tl][lane];
        size_t o = (size_t)(n * TT + t0 + tl) * CC + c0 + lane;
        __nv_bfloat16 h = __float2bfloat16(v);
        g_xhi[o] = h;
        g_xlo[o] = __float2bfloat16(v - __bfloat162float(h));
    }
}

// ===========================================================================
// HMMA (mma.sync m16n8k16 bf16) bf16x3 distance GEMM + fused argmin
//   CTA: 128 rows x 2048 codes (16 chunks of 128); K=512 in 16 tiles of 32.
//   8 warps = 4 row-groups x 2 col-groups; warp tile 32x64.
//   Fragment loads via ldmatrix.x4; 2 CTAs/SM.
// ===========================================================================
#define SC2_OFF   0          // 2048 f32 = 8192 B
#define MD1_OFF   8192       // 128 f32
#define MI1_OFF   8704       // 128 i32
#define MD2_OFF   9216       // 128 f32
#define MI2_OFF   9728       // 128 i32
#define STAGE0    10240
#define ROWB      80         // bytes per smem row (32 bf16 + 16B pad)
#define OFF_AH    0
#define OFF_AL    10240      // 128*80
#define OFF_BH    20480
#define OFF_BL    30720
#define STAGE_SZ  40960
#define SMEM_TOTAL_MMA (10240 + 2 * STAGE_SZ)   // 92160
#define THRESH 0.05f

__device__ __forceinline__ void load_tiles(uint32_t sb, int r0, int i) {
    const int tid = threadIdx.x;
    const int kt = i & 15;          // k-tile (32 elems)
    const int cc = i >> 4;          // code chunk (128 codes)
    const uint32_t stage = sb + STAGE0 + (uint32_t)(i & 1) * STAGE_SZ;
    const int kofs = kt << 5;
    #pragma unroll
    for (int u = 0; u < 2; u++) {
        int idx = tid + (u << 8);
        int row = idx >> 2, c16 = idx & 3;
        uint32_t off = (uint32_t)(row * ROWB + c16 * 16);
        size_t ga = (size_t)(r0 + row) * CC + kofs + (c16 << 3);
        cp16(stage + OFF_AH + off, &g_xhi[ga]);
        cp16(stage + OFF_AL + off, &g_xlo[ga]);
        size_t gb = (size_t)((cc << 7) + row) * CC + kofs + (c16 << 3);
        cp16(stage + OFF_BH + off, &g_cbhi[gb]);
        cp16(stage + OFF_BL + off, &g_cblo[gb]);
    }
}

__device__ __forceinline__ void upd2(float& d1, int& i1, float& d2, int& i2,
                                     float d, int code) {
    if (d < d1)      { d2 = d1; i2 = i1; d1 = d; i1 = code; }
    else if (d < d2) { d2 = d; i2 = code; }
}
__device__ __forceinline__ void merge2(float& d1, int& i1, float& d2, int& i2,
                                       float od1, int oi1, float od2, int oi2) {
    if (od1 < d1 || (od1 == d1 && oi1 < i1)) {
        if (d1 < od2 || (d1 == od2 && i1 < oi2)) { d2 = d1; i2 = i1; }
        else                                      { d2 = od2; i2 = oi2; }
        d1 = od1; i1 = oi1;
    } else {
        if (od1 < d2 || (od1 == d2 && oi1 < i2)) { d2 = od1; i2 = oi1; }
    }
}

__global__ __launch_bounds__(256, 2) void mma_argmin_kernel() {
    extern __shared__ char smem[];
    const uint32_t sb = smem_to_u32(smem);
    const int tid = threadIdx.x;
    const int wid = tid >> 5;
    const int lane = tid & 31;
    const int wr = (wid >> 1) * 32;     // warp row offset (0/32/64/96)
    const int wc = (wid & 1) * 64;      // warp col offset (0/64)
    const int g = lane >> 2;            // 0..7
    const int q = lane & 3;             // 0..3
    const int r0 = blockIdx.x * 128;

    // ldmatrix per-lane base offsets (within a stage)
    const int lrow = lane & 7;
    const int lm = lane >> 3;
    const uint32_t a_base = (uint32_t)((wr + (lm & 1) * 8 + lrow) * ROWB + (lm >> 1) * 16);
    const uint32_t b_base = (uint32_t)((wc + (lm >> 1) * 8 + lrow) * ROWB + (lm & 1) * 16);

    float* sc2 = (float*)(smem + SC2_OFF);
    for (int c = tid; c < NB; c += 256) sc2[c] = g_c2[c];

    float acc[2][8][4];
    float bd1[4], bd2[4]; int bi1[4], bi2[4];
    #pragma unroll
    for (int s = 0; s < 4; s++) { bd1[s] = FLT_MAX; bd2[s] = FLT_MAX; bi1[s] = 0; bi2[s] = 0; }

    load_tiles(sb, r0, 0);
    asm volatile("cp.async.commit_group;" ::: "memory");

    for (int i = 0; i < 256; i++) {
        const int kt = i & 15;
        const int cc = i >> 4;
        if (i + 1 < 256) {
            load_tiles(sb, r0, i + 1);
            asm volatile("cp.async.commit_group;" ::: "memory");
            asm volatile("cp.async.wait_group 1;" ::: "memory");
        } else {
            asm volatile("cp.async.wait_group 0;" ::: "memory");
        }
        __syncthreads();

        if (kt == 0) {
            #pragma unroll
            for (int mt = 0; mt < 2; mt++)
                #pragma unroll
                for (int nt = 0; nt < 8; nt++)
                    #pragma unroll
                    for (int r = 0; r < 4; r++) acc[mt][nt][r] = 0.f;
        }

        const uint32_t stage = sb + STAGE0 + (uint32_t)(i & 1) * STAGE_SZ;
        #pragma unroll
        for (int ks = 0; ks < 2; ks++) {
            const uint32_t ksb = ks * 32;
            uint32_t ah[2][4], al[2][4];
            #pragma unroll
            for (int mt = 0; mt < 2; mt++) {
                ldsm_x4(ah[mt], stage + OFF_AH + a_base + mt * (16 * ROWB) + ksb);
                ldsm_x4(al[mt], stage + OFF_AL + a_base + mt * (16 * ROWB) + ksb);
            }
            #pragma unroll
            for (int p = 0; p < 4; p++) {
                uint32_t bh[4], bl[4];
                ldsm_x4(bh, stage + OFF_BH + b_base + p * (16 * ROWB) + ksb);
                ldsm_x4(bl, stage + OFF_BL + b_base + p * (16 * ROWB) + ksb);
                #pragma unroll
                for (int mt = 0; mt < 2; mt++) {
                    mma16816(acc[mt][2 * p],     ah[mt], bh[0], bh[1]);   // xh*ch
                    mma16816(acc[mt][2 * p],     ah[mt], bl[0], bl[1]);   // xh*cl
                    mma16816(acc[mt][2 * p],     al[mt], bh[0], bh[1]);   // xl*ch
                    mma16816(acc[mt][2 * p + 1], ah[mt], bh[2], bh[3]);
                    mma16816(acc[mt][2 * p + 1], ah[mt], bl[2], bl[3]);
                    mma16816(acc[mt][2 * p + 1], al[mt], bh[2], bh[3]);
                }
            }
        }

        if (kt == 15) {
            // chunk epilogue: d = c2 - 2*dot; track best/second per row slot
            #pragma unroll
            for (int mt = 0; mt < 2; mt++) {
                #pragma unroll
                for (int nt = 0; nt < 8; nt++) {
                    int code0 = (cc << 7) + wc + nt * 8 + q * 2;
                    float c2a = sc2[code0], c2b = sc2[code0 + 1];
                    upd2(bd1[mt*2], bi1[mt*2], bd2[mt*2], bi2[mt*2],
                         c2a - 2.f * acc[mt][nt][0], code0);
                    upd2(bd1[mt*2], bi1[mt*2], bd2[mt*2], bi2[mt*2],
                         c2b - 2.f * acc[mt][nt][1], code0 + 1);
                    upd2(bd1[mt*2+1], bi1[mt*2+1], bd2[mt*2+1], bi2[mt*2+1],
                         c2a - 2.f * acc[mt][nt][2], code0);
                    upd2(bd1[mt*2+1], bi1[mt*2+1], bd2[mt*2+1], bi2[mt*2+1],
                         c2b - 2.f * acc[mt][nt][3], code0 + 1);
                }
            }
        }
        __syncthreads();
    }

    // reduce across the 4 lanes sharing each row (xor 1, 2)
    #pragma unroll
    for (int s = 0; s < 4; s++) {
        #pragma unroll
        for (int o = 1; o <= 2; o <<= 1) {
            float od1 = __shfl_xor_sync(0xffffffffu, bd1[s], o);
            int   oi1 = __shfl_xor_sync(0xffffffffu, bi1[s], o);
            float od2 = __shfl_xor_sync(0xffffffffu, bd2[s], o);
            int   oi2 = __shfl_xor_sync(0xffffffffu, bi2[s], o);
            merge2(bd1[s], bi1[s], bd2[s], bi2[s], od1, oi1, od2, oi2);
        }
    }

    float* md1 = (float*)(smem + MD1_OFF);
    int*   mi1 = (int*)  (smem + MI1_OFF);
    float* md2 = (float*)(smem + MD2_OFF);
    int*   mi2 = (int*)  (smem + MI2_OFF);

    if ((wid & 1) == 1 && q == 0) {
        #pragma unroll
        for (int s = 0; s < 4; s++) {
            int row = wr + (s >> 1) * 16 + (s & 1) * 8 + g;
            md1[row] = bd1[s]; mi1[row] = bi1[s];
            md2[row] = bd2[s]; mi2[row] = bi2[s];
        }
    }
    __syncthreads();
    if ((wid & 1) == 0 && q == 0) {
        #pragma unroll
        for (int s = 0; s < 4; s++) {
            int row = wr + (s >> 1) * 16 + (s & 1) * 8 + g;
            merge2(bd1[s], bi1[s], bd2[s], bi2[s],
                   md1[row], mi1[row], md2[row], mi2[row]);
            g_idx[r0 + row] = bi1[s];
            if (bd2[s] - bd1[s] < THRESH) {
                int pos = atomicAdd(&g_resc_cnt, 1);
                g_resc_row[pos] = r0 + row;
                g_resc_i1[pos]  = bi1[s];
                g_resc_i2[pos]  = bi2[s];
            }
        }
    }
}

// ===========================================================================
// Exact fp32 rescore of top-2 candidates for small-margin rows
// ===========================================================================
__global__ __launch_bounds__(256) void rescue_kernel(const float* __restrict__ x,
                                                     const float* __restrict__ cb) {
    const int cnt = g_resc_cnt;
    const int wid = threadIdx.x >> 5;
    const int lane = threadIdx.x & 31;
    for (int j = blockIdx.x * 8 + wid; j < cnt; j += gridDim.x * 8) {
        int row = g_resc_row[j], ia = g_resc_i1[j], ib = g_resc_i2[j];
        int n = row >> 10, t = row & 1023;
        const float* xr = x + (size_t)n * CTS + t;
        const float* ca = cb + (size_t)ia * CC;
        const float* cbp = cb + (size_t)ib * CC;
        float s1 = 0.f, s2 = 0.f;
        #pragma unroll 4
        for (int c = lane; c < CC; c += 32) {
            float xv = xr[(size_t)c * TT];
            s1 += xv * ca[c];
            s2 += xv * cbp[c];
        }
        #pragma unroll
        for (int o = 16; o; o >>= 1) {
            s1 += __shfl_xor_sync(0xffffffffu, s1, o);
            s2 += __shfl_xor_sync(0xffffffffu, s2, o);
        }
        if (lane == 0) {
            float da = g_c2[ia] - 2.f * s1;
            float db = g_c2[ib] - 2.f * s2;
            int best = (db < da || (db == da && ib < ia)) ? ib : ia;
            g_idx[row] = best;
        }
    }
}

// ===========================================================================
// Gather codebook rows -> x_d_out, segment sums, commit-loss
//   segment-sum now uses one red.global.v4.f32.add per (code, 4c) instead of
//   4 scalar atomics.
// ===========================================================================
__global__ __launch_bounds__(256) void scatter_kernel(const float* __restrict__ x,
                                                      const float* __restrict__ cb,
                                                      float* __restrict__ out) {
    __shared__ int   sidx[32];
    __shared__ float tile[32][33];
    __shared__ float red[8];

    const int b = blockIdx.x;
    const int n = b >> 5;
    const int t0 = (b & 31) * 32;
    const int tid = threadIdx.x;
    const int w = tid >> 5;
    const int lane = tid & 31;

    if (tid < 32) sidx[tid] = g_idx[n * TT + t0 + tid];
    __syncthreads();
    if (tid < 32) atomicAdd(&g_new_cnt[sidx[tid]], 1.0f);

    const int mycode = sidx[lane];   // code of row t0+lane (this thread's atomic target)

    float lsum = 0.f;
    for (int c0 = 0; c0 < CC; c0 += 32) {
        #pragma unroll
        for (int i = 0; i < 4; i++) {
            int t = w * 4 + i;
            tile[t][lane] = cb[(size_t)sidx[t] * CC + c0 + lane];
        }
        __syncthreads();
        float xs[4];
        #pragma unroll
        for (int i = 0; i < 4; i++) {
            int cr = w * 4 + i;
            int c = c0 + cr;
            size_t off = (size_t)n * CTS + (size_t)c * TT + t0 + lane;
            float xv = x[off];
            float v = tile[lane][cr];
            out[OUT_XD + off] = v;
            float dd = xv - v;
            lsum += dd * dd;
            xs[i] = xv;
        }
        // one vectorized reduction: 4 consecutive c for this thread's code
        float* dst = &g_new_sum[(size_t)mycode * CC + c0 + w * 4];
        asm volatile("red.global.v4.f32.add [%0], {%1,%2,%3,%4};"
                     :: "l"(dst), "f"(xs[0]), "f"(xs[1]), "f"(xs[2]), "f"(xs[3])
                     : "memory");
        __syncthreads();
    }

    #pragma unroll
    for (int o = 16; o; o >>= 1) lsum += __shfl_xor_sync(0xffffffffu, lsum, o);
    if (lane == 0) red[w] = lsum;
    __syncthreads();
    if (tid == 0) {
        float s = 0.f;
        #pragma unroll
        for (int i = 0; i < 8; i++) s += red[i];
        atomicAdd(&g_loss, (double)s);
    }
}

// ===========================================================================
// EMA updates, codebook reset, perplexity partials
// ===========================================================================
__global__ __launch_bounds__(128) void finalize_kernel(const float* __restrict__ x,
                                                       const float* __restrict__ code_sum,
                                                       const float* __restrict__ code_count,
                                                       float* __restrict__ out) {
    const int k = blockIdx.x;
    const int tid = threadIdx.x;
    float ncnt = g_new_cnt[k];
    float cnt_ema = MUF * code_count[k] + OMM * ncnt;
    bool usage = (cnt_ema >= 1.0f);
    float denom = fmaxf(cnt_ema, 1e-10f);

    for (int c = tid; c < CC; c += 128) {
        float sema = MUF * code_sum[(size_t)k * CC + c] + OMM * g_new_sum[(size_t)k * CC + c];
        out[OUT_SEMA + (size_t)k * CC + c] = sema;
        float v;
        if (usage) v = sema / denom;
        else       v = x[(size_t)(k >> 10) * CTS + (size_t)c * TT + (k & 1023)];
        out[OUT_CB + (size_t)k * CC + c] = v;
    }
    if (tid == 0) {
        out[OUT_CEMA + k] = cnt_ema;
        float p = ncnt / 32768.0f;
        atomicAdd(&g_plx, p * logf(p + 1e-7f));
    }
}

__global__ void scalars_kernel(float* __restrict__ out) {
    out[OUT_LOSS] = (float)(g_loss * (1.0 / 16777216.0));
    out[OUT_PLX] = expf(-g_plx);
}

// ===========================================================================
extern "C" void kernel_launch(void* const* d_in, const int* in_sizes, int n_in,
                              void* d_out, int out_size) {
    const float* x    = (const float*)d_in[0];
    const float* cb   = (const float*)d_in[1];
    const float* csum = (const float*)d_in[2];
    const float* ccnt = (const float*)d_in[3];
    float* out = (float*)d_out;

    cudaFuncSetAttribute(mma_argmin_kernel,
                         cudaFuncAttributeMaxDynamicSharedMemorySize, SMEM_TOTAL_MMA);

    zero_kernel<<<(NB * CC + 255) / 256, 256>>>();
    c2_kernel<<<(NB * 32 + 255) / 256, 256>>>(cb);
    cvtcb_kernel<<<(NB * CC + 255) / 256, 256>>>(cb);
    cvtx_kernel<<<NN * 512, 256>>>(x);
    mma_argmin_kernel<<<NT / 128, 256, SMEM_TOTAL_MMA>>>();
    rescue_kernel<<<128, 256>>>(x, cb);
    scatter_kernel<<<NN * (TT / 32), 256>>>(x, cb, out);
    finalize_kernel<<<NB, 128>>>(x, csum, ccnt, out);
    scalars_kernel<<<1, 1>>>(out);
}

// round 14
// speedup vs baseline: 2.8512x; 1.1173x over previous
#include <cuda_runtime.h>
#include <cuda_bf16.h>
#include <math.h>
#include <float.h>
#include <stdint.h>

// Problem constants (fixed shapes per reference)
#define NN   32
#define CC   512
#define TT   1024
#define NT   32768      // NN*TT rows of x_flat
#define NB   2048       // codebook entries
#define CTS  524288     // CC*TT

static constexpr float MUF = 0.99f;
static constexpr float OMM = (float)(1.0 - 0.99);

// Output layout: tuple concatenated in return order, all fp32
#define OUT_XD    0
#define OUT_LOSS  16777216
#define OUT_PLX   16777217
#define OUT_CB    16777218
#define OUT_SEMA  (16777218 + 1048576)
#define OUT_CEMA  (17825794 + 1048576)

// Scratch (static device globals — no allocation)
__device__ float  g_new_sum[NB * CC];
__device__ float  g_new_cnt[NB];
__device__ int    g_idx[NT];
__device__ float  g_c2[NB];
__device__ double g_loss;
__device__ float  g_plx;

__device__ __align__(16) __nv_bfloat16 g_xhi[(size_t)NT * CC];
__device__ __align__(16) __nv_bfloat16 g_xlo[(size_t)NT * CC];
__device__ __align__(16) __nv_bfloat16 g_cbhi[(size_t)NB * CC];
__device__ __align__(16) __nv_bfloat16 g_cblo[(size_t)NB * CC];
__device__ int g_resc_cnt;
__device__ int g_resc_row[NT];
__device__ int g_resc_i1[NT];
__device__ int g_resc_i2[NT];

// ===========================================================================
__device__ __forceinline__ uint32_t smem_to_u32(const void* p) {
    uint32_t a;
    asm("{ .reg .u64 t; cvta.to.shared.u64 t, %1; cvt.u32.u64 %0, t; }" : "=r"(a) : "l"(p));
    return a;
}
__device__ __forceinline__ void cp16(uint32_t dst, const void* src) {
    asm volatile("cp.async.cg.shared.global [%0], [%1], 16;" :: "r"(dst), "l"(src));
}
__device__ __forceinline__ void mma16816(float* c, const uint32_t* a, uint32_t b0, uint32_t b1) {
    asm volatile(
        "mma.sync.aligned.m16n8k16.row.col.f32.bf16.bf16.f32 "
        "{%0,%1,%2,%3}, {%4,%5,%6,%7}, {%8,%9}, {%0,%1,%2,%3};"
        : "+f"(c[0]), "+f"(c[1]), "+f"(c[2]), "+f"(c[3])
        : "r"(a[0]), "r"(a[1]), "r"(a[2]), "r"(a[3]), "r"(b0), "r"(b1));
}
__device__ __forceinline__ void ldsm_x4(uint32_t* r, uint32_t addr) {
    asm volatile("ldmatrix.sync.aligned.m8n8.x4.shared.b16 {%0,%1,%2,%3}, [%4];"
        : "=r"(r[0]), "=r"(r[1]), "=r"(r[2]), "=r"(r[3]) : "r"(addr));
}

// ===========================================================================
// Fused prologue: codebook split + c2 + scratch zeroing.  One block per code.
// ===========================================================================
__global__ __launch_bounds__(128) void prep_cb(const float* __restrict__ cb) {
    const int k = blockIdx.x;
    const int tid = threadIdx.x;
    const int w = tid >> 5, lane = tid & 31;
    __shared__ float red[4];
    float s = 0.f;
    #pragma unroll
    for (int j = 0; j < 4; j++) {
        int c = tid + j * 128;
        float v = cb[(size_t)k * CC + c];
        __nv_bfloat16 h = __float2bfloat16(v);
        g_cbhi[(size_t)k * CC + c] = h;
        g_cblo[(size_t)k * CC + c] = __float2bfloat16(v - __bfloat162float(h));
        g_new_sum[(size_t)k * CC + c] = 0.f;
        s += v * v;
    }
    #pragma unroll
    for (int o = 16; o; o >>= 1) s += __shfl_xor_sync(0xffffffffu, s, o);
    if (lane == 0) red[w] = s;
    __syncthreads();
    if (tid == 0) g_c2[k] = red[0] + red[1] + red[2] + red[3];
    if (tid == 1) g_new_cnt[k] = 0.f;
    if (k == 0 && tid == 2) { g_loss = 0.0; g_plx = 0.f; g_resc_cnt = 0; }
}

// x split + transpose: x(N,C,T) -> row-major x_flat[row=n*T+t][c], bf16 hi/lo
__global__ __launch_bounds__(256) void cvtx_kernel(const float* __restrict__ x) {
    __shared__ float tile[32][33];
    int b = blockIdx.x;
    int n   = b >> 9;
    int rem = b & 511;
    int t0 = (rem >> 4) << 5;
    int c0 = (rem & 15) << 5;
    int w = threadIdx.x >> 5, lane = threadIdx.x & 31;
    #pragma unroll
    for (int i = 0; i < 4; i++) {
        int cl = w * 4 + i;
        tile[lane][cl] = x[(size_t)n * CTS + (size_t)(c0 + cl) * TT + t0 + lane];
    }
    __syncthreads();
    #pragma unroll
    for (int i = 0; i < 4; i++) {
        int tl = w * 4 + i;
        float v = tile[tl][lane];
        size_t o = (size_t)(n * TT + t0 + tl) * CC + c0 + lane;
        __nv_bfloat16 h = __float2bfloat16(v);
        g_xhi[o] = h;
        g_xlo[o] = __float2bfloat16(v - __bfloat162float(h));
    }
}

// ===========================================================================
// HMMA bf16x3 distance GEMM + fused argmin
//   CTA: 128 rows x 2048 codes (16 chunks of 128); K=512 in 16 tiles of 32.
//   8 warps = 4 row-groups x 2 col-groups; warp tile 32x64; ldmatrix frags.
//   Compact SW128-swizzled stages (A/B tiles, hi|lo interleaved in 128B rows),
//   3-stage cp.async pipeline, one barrier per iter, 2 CTAs/SM.
// ===========================================================================
#define SC2_OFF   0          // 2048 f32 = 8192 B
#define MD1_OFF   8192       // 128 f32
#define MI1_OFF   8704       // 128 i32
#define MD2_OFF   9216       // 128 f32
#define MI2_OFF   9728       // 128 i32
#define STAGE0    10240
#define OFF_B     16384      // B tile within a stage (A at 0)
#define STAGE_SZ  32768
#define N_STAGE   3
#define SMEM_TOTAL_MMA (STAGE0 + N_STAGE * STAGE_SZ)   // 108544
#define THRESH 0.05f

// Stage row layout: 128B per (smem-row, k32-tile): chunks 0-3 = hi (8 bf16 each),
// chunks 4-7 = lo.  Swizzle: chunk ^= (row & 7).
__device__ __forceinline__ void load_tiles(uint32_t sb, int r0, int i) {
    const int tid = threadIdx.x;
    const int lchunk = tid & 7;                 // fixed per thread
    const int lrow0 = tid >> 3;                 // 0..31
    const uint32_t xorc = (uint32_t)((lchunk ^ (lrow0 & 7)) << 4);
    const bool ishi = lchunk < 4;
    const int ksub = (lchunk & 3) * 8;          // k offset within 32-tile
    const int kofs = (i & 15) << 5;
    const int cc = i >> 4;
    const uint32_t stage = sb + STAGE0 + (uint32_t)(i % N_STAGE) * STAGE_SZ;
    #pragma unroll
    for (int u = 0; u < 4; u++) {               // A rows
        int srow = lrow0 + u * 32;
        size_t g = (size_t)(r0 + srow) * CC + kofs + ksub;
        cp16(stage + (uint32_t)(srow * 128) + xorc, ishi ? (const void*)&g_xhi[g] : (const void*)&g_xlo[g]);
    }
    #pragma unroll
    for (int u = 0; u < 4; u++) {               // B rows (codes)
        int srow = lrow0 + u * 32;
        size_t g = (size_t)((cc << 7) + srow) * CC + kofs + ksub;
        cp16(stage + OFF_B + (uint32_t)(srow * 128) + xorc, ishi ? (const void*)&g_cbhi[g] : (const void*)&g_cblo[g]);
    }
}

__device__ __forceinline__ void upd2(float& d1, int& i1, float& d2, int& i2,
                                     float d, int code) {
    if (d < d1)      { d2 = d1; i2 = i1; d1 = d; i1 = code; }
    else if (d < d2) { d2 = d; i2 = code; }
}
__device__ __forceinline__ void merge2(float& d1, int& i1, float& d2, int& i2,
                                       float od1, int oi1, float od2, int oi2) {
    if (od1 < d1 || (od1 == d1 && oi1 < i1)) {
        if (d1 < od2 || (d1 == od2 && i1 < oi2)) { d2 = d1; i2 = i1; }
        else                                      { d2 = od2; i2 = oi2; }
        d1 = od1; i1 = oi1;
    } else {
        if (od1 < d2 || (od1 == d2 && oi1 < i2)) { d2 = od1; i2 = oi1; }
    }
}

__global__ __launch_bounds__(256, 2) void mma_argmin_kernel() {
    extern __shared__ char smem[];
    const uint32_t sb = smem_to_u32(smem);
    const int tid = threadIdx.x;
    const int wid = tid >> 5;
    const int lane = tid & 31;
    const int wr = (wid >> 1) * 32;     // warp row offset (0/32/64/96)
    const int wc = (wid & 1) * 64;      // warp col offset (0/64)
    const int g = lane >> 2;            // 0..7
    const int q = lane & 3;             // 0..3
    const int r0 = blockIdx.x * 128;

    // ldmatrix per-lane geometry (same logical mapping as before; swizzled addrs)
    const int lrow = lane & 7;
    const int lm = lane >> 3;
    const int arow = wr + (lm & 1) * 8 + lrow;     // A: rows of x tile
    const int asel = lm >> 1;                      // A chunk select 0/1
    const int brow = wc + (lm >> 1) * 8 + lrow;    // B: rows of code tile
    const int bsel = lm & 1;                       // B chunk select 0/1
    const uint32_t arowb = (uint32_t)(arow * 128);
    const int axor = arow & 7;
    const uint32_t browb = (uint32_t)(brow * 128);
    const int bxor = brow & 7;

    float* sc2 = (float*)(smem + SC2_OFF);
    for (int c = tid; c < NB; c += 256) sc2[c] = g_c2[c];

    float acc[2][8][4];
    float bd1[4], bd2[4]; int bi1[4], bi2[4];
    #pragma unroll
    for (int s = 0; s < 4; s++) { bd1[s] = FLT_MAX; bd2[s] = FLT_MAX; bi1[s] = 0; bi2[s] = 0; }

    load_tiles(sb, r0, 0);
    asm volatile("cp.async.commit_group;" ::: "memory");
    load_tiles(sb, r0, 1);
    asm volatile("cp.async.commit_group;" ::: "memory");

    for (int i = 0; i < 256; i++) {
        const int kt = i & 15;
        const int cc = i >> 4;

        if (i < 255) asm volatile("cp.async.wait_group 1;" ::: "memory");
        else         asm volatile("cp.async.wait_group 0;" ::: "memory");
        __syncthreads();
        if (i + 2 < 256) {
            load_tiles(sb, r0, i + 2);
            asm volatile("cp.async.commit_group;" ::: "memory");
        }

        if (kt == 0) {
            #pragma unroll
            for (int mt = 0; mt < 2; mt++)
                #pragma unroll
                for (int nt = 0; nt < 8; nt++)
                    #pragma unroll
                    for (int r = 0; r < 4; r++) acc[mt][nt][r] = 0.f;
        }

        const uint32_t stage = sb + STAGE0 + (uint32_t)(i % N_STAGE) * STAGE_SZ;
        #pragma unroll
        for (int ks = 0; ks < 2; ks++) {
            const uint32_t ahoff = arowb + (uint32_t)((((ks << 1) + asel)     ^ axor) << 4);
            const uint32_t aloff = arowb + (uint32_t)((((ks << 1) + asel + 4) ^ axor) << 4);
            uint32_t ah[2][4], al[2][4];
            ldsm_x4(ah[0], stage + ahoff);
            ldsm_x4(ah[1], stage + ahoff + 2048);   // rows +16
            ldsm_x4(al[0], stage + aloff);
            ldsm_x4(al[1], stage + aloff + 2048);
            const uint32_t bhoff = browb + (uint32_t)((((ks << 1) + bsel)     ^ bxor) << 4);
            const uint32_t bloff = browb + (uint32_t)((((ks << 1) + bsel + 4) ^ bxor) << 4);
            #pragma unroll
            for (int p = 0; p < 4; p++) {
                uint32_t bh[4], bl[4];
                ldsm_x4(bh, stage + OFF_B + bhoff + p * 2048);
                ldsm_x4(bl, stage + OFF_B + bloff + p * 2048);
                #pragma unroll
                for (int mt = 0; mt < 2; mt++) {
                    mma16816(acc[mt][2 * p],     ah[mt], bh[0], bh[1]);   // xh*ch
                    mma16816(acc[mt][2 * p],     ah[mt], bl[0], bl[1]);   // xh*cl
                    mma16816(acc[mt][2 * p],     al[mt], bh[0], bh[1]);   // xl*ch
                    mma16816(acc[mt][2 * p + 1], ah[mt], bh[2], bh[3]);
                    mma16816(acc[mt][2 * p + 1], ah[mt], bl[2], bl[3]);
                    mma16816(acc[mt][2 * p + 1], al[mt], bh[2], bh[3]);
                }
            }
        }

        if (kt == 15) {
            // chunk epilogue: d = c2 - 2*dot; track best/second per row slot
            #pragma unroll
            for (int mt = 0; mt < 2; mt++) {
                #pragma unroll
                for (int nt = 0; nt < 8; nt++) {
                    int code0 = (cc << 7) + wc + nt * 8 + q * 2;
                    float c2a = sc2[code0], c2b = sc2[code0 + 1];
                    upd2(bd1[mt*2], bi1[mt*2], bd2[mt*2], bi2[mt*2],
                         c2a - 2.f * acc[mt][nt][0], code0);
                    upd2(bd1[mt*2], bi1[mt*2], bd2[mt*2], bi2[mt*2],
                         c2b - 2.f * acc[mt][nt][1], code0 + 1);
                    upd2(bd1[mt*2+1], bi1[mt*2+1], bd2[mt*2+1], bi2[mt*2+1],
                         c2a - 2.f * acc[mt][nt][2], code0);
                    upd2(bd1[mt*2+1], bi1[mt*2+1], bd2[mt*2+1], bi2[mt*2+1],
                         c2b - 2.f * acc[mt][nt][3], code0 + 1);
                }
            }
        }
    }

    // reduce across the 4 lanes sharing each row (xor 1, 2)
    #pragma unroll
    for (int s = 0; s < 4; s++) {
        #pragma unroll
        for (int o = 1; o <= 2; o <<= 1) {
            float od1 = __shfl_xor_sync(0xffffffffu, bd1[s], o);
            int   oi1 = __shfl_xor_sync(0xffffffffu, bi1[s], o);
            float od2 = __shfl_xor_sync(0xffffffffu, bd2[s], o);
            int   oi2 = __shfl_xor_sync(0xffffffffu, bi2[s], o);
            merge2(bd1[s], bi1[s], bd2[s], bi2[s], od1, oi1, od2, oi2);
        }
    }

    float* md1 = (float*)(smem + MD1_OFF);
    int*   mi1 = (int*)  (smem + MI1_OFF);
    float* md2 = (float*)(smem + MD2_OFF);
    int*   mi2 = (int*)  (smem + MI2_OFF);

    __syncthreads();
    if ((wid & 1) == 1 && q == 0) {
        #pragma unroll
        for (int s = 0; s < 4; s++) {
            int row = wr + (s >> 1) * 16 + (s & 1) * 8 + g;
            md1[row] = bd1[s]; mi1[row] = bi1[s];
            md2[row] = bd2[s]; mi2[row] = bi2[s];
        }
    }
    __syncthreads();
    if ((wid & 1) == 0 && q == 0) {
        #pragma unroll
        for (int s = 0; s < 4; s++) {
            int row = wr + (s >> 1) * 16 + (s & 1) * 8 + g;
            merge2(bd1[s], bi1[s], bd2[s], bi2[s],
                   md1[row], mi1[row], md2[row], mi2[row]);
            g_idx[r0 + row] = bi1[s];
            if (bd2[s] - bd1[s] < THRESH) {
                int pos = atomicAdd(&g_resc_cnt, 1);
                g_resc_row[pos] = r0 + row;
                g_resc_i1[pos]  = bi1[s];
                g_resc_i2[pos]  = bi2[s];
            }
        }
    }
}

// ===========================================================================
// Exact fp32 rescore of top-2 candidates for small-margin rows
// ===========================================================================
__global__ __launch_bounds__(256) void rescue_kernel(const float* __restrict__ x,
                                                     const float* __restrict__ cb) {
    const int cnt = g_resc_cnt;
    const int wid = threadIdx.x >> 5;
    const int lane = threadIdx.x & 31;
    for (int j = blockIdx.x * 8 + wid; j < cnt; j += gridDim.x * 8) {
        int row = g_resc_row[j], ia = g_resc_i1[j], ib = g_resc_i2[j];
        int n = row >> 10, t = row & 1023;
        const float* xr = x + (size_t)n * CTS + t;
        const float* ca = cb + (size_t)ia * CC;
        const float* cbp = cb + (size_t)ib * CC;
        float s1 = 0.f, s2 = 0.f;
        #pragma unroll 4
        for (int c = lane; c < CC; c += 32) {
            float xv = xr[(size_t)c * TT];
            s1 += xv * ca[c];
            s2 += xv * cbp[c];
        }
        #pragma unroll
        for (int o = 16; o; o >>= 1) {
            s1 += __shfl_xor_sync(0xffffffffu, s1, o);
            s2 += __shfl_xor_sync(0xffffffffu, s2, o);
        }
        if (lane == 0) {
            float da = g_c2[ia] - 2.f * s1;
            float db = g_c2[ib] - 2.f * s2;
            int best = (db < da || (db == da && ib < ia)) ? ib : ia;
            g_idx[row] = best;
        }
    }
}

// ===========================================================================
// Gather codebook rows -> x_d_out, segment sums, commit-loss
// ===========================================================================
__global__ __launch_bounds__(256) void scatter_kernel(const float* __restrict__ x,
                                                      const float* __restrict__ cb,
                                                      float* __restrict__ out) {
    __shared__ int   sidx[32];
    __shared__ float tile[32][33];
    __shared__ float red[8];

    const int b = blockIdx.x;
    const int n = b >> 5;
    const int t0 = (b & 31) * 32;
    const int tid = threadIdx.x;
    const int w = tid >> 5;
    const int lane = tid & 31;

    if (tid < 32) sidx[tid] = g_idx[n * TT + t0 + tid];
    __syncthreads();
    if (tid < 32) atomicAdd(&g_new_cnt[sidx[tid]], 1.0f);

    const int mycode = sidx[lane];   // code of row t0+lane (this thread's atomic target)

    float lsum = 0.f;
    for (int c0 = 0; c0 < CC; c0 += 32) {
        #pragma unroll
        for (int i = 0; i < 4; i++) {
            int t = w * 4 + i;
            tile[t][lane] = cb[(size_t)sidx[t] * CC + c0 + lane];
        }
        __syncthreads();
        float xs[4];
        #pragma unroll
        for (int i = 0; i < 4; i++) {
            int cr = w * 4 + i;
            int c = c0 + cr;
            size_t off = (size_t)n * CTS + (size_t)c * TT + t0 + lane;
            float xv = x[off];
            float v = tile[lane][cr];
            out[OUT_XD + off] = v;
            float dd = xv - v;
            lsum += dd * dd;
            xs[i] = xv;
        }
        // one vectorized reduction: 4 consecutive c for this thread's code
        float* dst = &g_new_sum[(size_t)mycode * CC + c0 + w * 4];
        asm volatile("red.global.v4.f32.add [%0], {%1,%2,%3,%4};"
                     :: "l"(dst), "f"(xs[0]), "f"(xs[1]), "f"(xs[2]), "f"(xs[3])
                     : "memory");
        __syncthreads();
    }

    #pragma unroll
    for (int o = 16; o; o >>= 1) lsum += __shfl_xor_sync(0xffffffffu, lsum, o);
    if (lane == 0) red[w] = lsum;
    __syncthreads();
    if (tid == 0) {
        float s = 0.f;
        #pragma unroll
        for (int i = 0; i < 8; i++) s += red[i];
        atomicAdd(&g_loss, (double)s);
    }
}

// ===========================================================================
// EMA updates, codebook reset, perplexity partials
// ===========================================================================
__global__ __launch_bounds__(128) void finalize_kernel(const float* __restrict__ x,
                                                       const float* __restrict__ code_sum,
                                                       const float* __restrict__ code_count,
                                                       float* __restrict__ out) {
    const int k = blockIdx.x;
    const int tid = threadIdx.x;
    float ncnt = g_new_cnt[k];
    float cnt_ema = MUF * code_count[k] + OMM * ncnt;
    bool usage = (cnt_ema >= 1.0f);
    float denom = fmaxf(cnt_ema, 1e-10f);

    for (int c = tid; c < CC; c += 128) {
        float sema = MUF * code_sum[(size_t)k * CC + c] + OMM * g_new_sum[(size_t)k * CC + c];
        out[OUT_SEMA + (size_t)k * CC + c] = sema;
        float v;
        if (usage) v = sema / denom;
        else       v = x[(size_t)(k >> 10) * CTS + (size_t)c * TT + (k & 1023)];
        out[OUT_CB + (size_t)k * CC + c] = v;
    }
    if (tid == 0) {
        out[OUT_CEMA + k] = cnt_ema;
        float p = ncnt / 32768.0f;
        atomicAdd(&g_plx, p * logf(p + 1e-7f));
    }
}

__global__ void scalars_kernel(float* __restrict__ out) {
    out[OUT_LOSS] = (float)(g_loss * (1.0 / 16777216.0));
    out[OUT_PLX] = expf(-g_plx);
}

// ===========================================================================
extern "C" void kernel_launch(void* const* d_in, const int* in_sizes, int n_in,
                              void* d_out, int out_size) {
    const float* x    = (const float*)d_in[0];
    const float* cb   = (const float*)d_in[1];
    const float* csum = (const float*)d_in[2];
    const float* ccnt = (const float*)d_in[3];
    float* out = (float*)d_out;

    cudaFuncSetAttribute(mma_argmin_kernel,
                         cudaFuncAttributeMaxDynamicSharedMemorySize, SMEM_TOTAL_MMA);

    prep_cb<<<NB, 128>>>(cb);
    cvtx_kernel<<<NN * 512, 256>>>(x);
    mma_argmin_kernel<<<NT / 128, 256, SMEM_TOTAL_MMA>>>();
    rescue_kernel<<<128, 256>>>(x, cb);
    scatter_kernel<<<NN * (TT / 32), 256>>>(x, cb, out);
    finalize_kernel<<<NB, 128>>>(x, csum, ccnt, out);
    scalars_kernel<<<1, 1>>>(out);
}

// round 16
// speedup vs baseline: 4.3787x; 1.5357x over previous
#include <cuda_runtime.h>
#include <cuda_fp16.h>
#include <math.h>
#include <float.h>
#include <stdint.h>

// Problem constants (fixed shapes per reference)
#define NN   32
#define CC   512
#define TT   1024
#define NT   32768      // NN*TT rows of x_flat
#define NB   2048       // codebook entries
#define CTS  524288     // CC*TT

static constexpr float MUF = 0.99f;
static constexpr float OMM = (float)(1.0 - 0.99);

// Output layout: tuple concatenated in return order, all fp32
#define OUT_XD    0
#define OUT_LOSS  16777216
#define OUT_PLX   16777217
#define OUT_CB    16777218
#define OUT_SEMA  (16777218 + 1048576)
#define OUT_CEMA  (17825794 + 1048576)

// Scratch (static device globals — no allocation)
__device__ float  g_new_sum[NB * CC];
__device__ float  g_new_cnt[NB];
__device__ int    g_idx[NT];
__device__ float  g_c2[NB];
__device__ double g_loss;
__device__ float  g_plx;

__device__ __align__(16) __half g_xf16[(size_t)NT * CC];
__device__ __align__(16) __half g_cbf16[(size_t)NB * CC];
__device__ int g_resc_cnt;
__device__ int g_resc_row[NT];
__device__ int g_resc_i1[NT];
__device__ int g_resc_i2[NT];
__device__ int g_resc_i3[NT];

// ===========================================================================
__device__ __forceinline__ uint32_t smem_to_u32(const void* p) {
    uint32_t a;
    asm("{ .reg .u64 t; cvta.to.shared.u64 t, %1; cvt.u32.u64 %0, t; }" : "=r"(a) : "l"(p));
    return a;
}
__device__ __forceinline__ void cp16(uint32_t dst, const void* src) {
    asm volatile("cp.async.cg.shared.global [%0], [%1], 16;" :: "r"(dst), "l"(src));
}
__device__ __forceinline__ void mma16816(float* c, const uint32_t* a, uint32_t b0, uint32_t b1) {
    asm volatile(
        "mma.sync.aligned.m16n8k16.row.col.f32.f16.f16.f32 "
        "{%0,%1,%2,%3}, {%4,%5,%6,%7}, {%8,%9}, {%0,%1,%2,%3};"
        : "+f"(c[0]), "+f"(c[1]), "+f"(c[2]), "+f"(c[3])
        : "r"(a[0]), "r"(a[1]), "r"(a[2]), "r"(a[3]), "r"(b0), "r"(b1));
}
__device__ __forceinline__ void ldsm_x4(uint32_t* r, uint32_t addr) {
    asm volatile("ldmatrix.sync.aligned.m8n8.x4.shared.b16 {%0,%1,%2,%3}, [%4];"
        : "=r"(r[0]), "=r"(r[1]), "=r"(r[2]), "=r"(r[3]) : "r"(addr));
}

// ===========================================================================
// Fused prologue: codebook fp16 convert + c2 + scratch zeroing. One block/code.
// ===========================================================================
__global__ __launch_bounds__(128) void prep_cb(const float* __restrict__ cb) {
    const int k = blockIdx.x;
    const int tid = threadIdx.x;
    const int w = tid >> 5, lane = tid & 31;
    __shared__ float red[4];
    float s = 0.f;
    #pragma unroll
    for (int j = 0; j < 4; j++) {
        int c = tid + j * 128;
        float v = cb[(size_t)k * CC + c];
        g_cbf16[(size_t)k * CC + c] = __float2half_rn(v);
        g_new_sum[(size_t)k * CC + c] = 0.f;
        s += v * v;
    }
    #pragma unroll
    for (int o = 16; o; o >>= 1) s += __shfl_xor_sync(0xffffffffu, s, o);
    if (lane == 0) red[w] = s;
    __syncthreads();
    if (tid == 0) g_c2[k] = red[0] + red[1] + red[2] + red[3];
    if (tid == 1) g_new_cnt[k] = 0.f;
    if (k == 0 && tid == 2) { g_loss = 0.0; g_plx = 0.f; g_resc_cnt = 0; }
}

// x convert + transpose: x(N,C,T) -> row-major x_flat[row=n*T+t][c], fp16
__global__ __launch_bounds__(256) void cvtx_kernel(const float* __restrict__ x) {
    __shared__ float tile[32][33];
    int b = blockIdx.x;
    int n   = b >> 9;
    int rem = b & 511;
    int t0 = (rem >> 4) << 5;
    int c0 = (rem & 15) << 5;
    int w = threadIdx.x >> 5, lane = threadIdx.x & 31;
    #pragma unroll
    for (int i = 0; i < 4; i++) {
        int cl = w * 4 + i;
        tile[lane][cl] = x[(size_t)n * CTS + (size_t)(c0 + cl) * TT + t0 + lane];
    }
    __syncthreads();
    #pragma unroll
    for (int i = 0; i < 4; i++) {
        int tl = w * 4 + i;
        float v = tile[tl][lane];
        size_t o = (size_t)(n * TT + t0 + tl) * CC + c0 + lane;
        g_xf16[o] = __float2half_rn(v);
    }
}

// ===========================================================================
// Single-pass fp16 HMMA distance GEMM + fused top-3 argmin
//   CTA: 128 rows x 2048 codes (16 chunks of 128); K=512 in 16 tiles of 32.
//   8 warps = 4 row-groups x 2 col-groups; warp tile 32x64; ldmatrix frags.
//   Compact stages: A 8KB + B 8KB per k32-tile (64B rows, chunk^((row>>1)&3)
//   swizzle). 5-stage cp.async pipeline, 2 CTAs/SM.
//   Exactness: rows with (d2-d1) < THRESH get top-3 exact fp32 rescore.
// ===========================================================================
#define SC2_OFF   0          // 2048 f32 = 8192 B
#define STAGE0    8192
#define OFF_B     8192       // B tile within a stage (A at 0)
#define STAGE_SZ  16384
#define N_STAGE   5
#define SMEM_TOTAL_MMA (STAGE0 + N_STAGE * STAGE_SZ)   // 90112
// merge arrays overlay the stage area after the mainloop:
#define SM_MD     8192       // 3 x 128 f32
#define SM_MI     (8192 + 1536)
#define THRESH 0.25f

__device__ __forceinline__ void load_tiles(uint32_t sb, int r0, int i) {
    const int tid = threadIdx.x;
    const int kofs = (i & 15) << 5;
    const int cc = i >> 4;
    const uint32_t stage = sb + STAGE0 + (uint32_t)(i % N_STAGE) * STAGE_SZ;
    #pragma unroll
    for (int u2 = 0; u2 < 2; u2++) {           // A: 512 16B-units
        int u = tid + (u2 << 8);
        int row = u >> 2, ch = u & 3;
        uint32_t off = (uint32_t)(row * 64 + ((ch ^ ((row >> 1) & 3)) << 4));
        cp16(stage + off, &g_xf16[(size_t)(r0 + row) * CC + kofs + ch * 8]);
    }
    #pragma unroll
    for (int u2 = 0; u2 < 2; u2++) {           // B: 512 16B-units
        int u = tid + (u2 << 8);
        int row = u >> 2, ch = u & 3;
        uint32_t off = (uint32_t)(row * 64 + ((ch ^ ((row >> 1) & 3)) << 4));
        cp16(stage + OFF_B + off, &g_cbf16[(size_t)((cc << 7) + row) * CC + kofs + ch * 8]);
    }
}

// top-3 insertion with first-index tie-break
__device__ __forceinline__ void ins3(float* d, int* ix, float nd, int ni) {
    if (nd < d[0] || (nd == d[0] && ni < ix[0])) {
        d[2] = d[1]; ix[2] = ix[1];
        d[1] = d[0]; ix[1] = ix[0];
        d[0] = nd;   ix[0] = ni;
    } else if (nd < d[1] || (nd == d[1] && ni < ix[1])) {
        d[2] = d[1]; ix[2] = ix[1];
        d[1] = nd;   ix[1] = ni;
    } else if (nd < d[2] || (nd == d[2] && ni < ix[2])) {
        d[2] = nd;   ix[2] = ni;
    }
}

__global__ __launch_bounds__(256, 2) void mma_argmin_kernel() {
    extern __shared__ char smem[];
    const uint32_t sb = smem_to_u32(smem);
    const int tid = threadIdx.x;
    const int wid = tid >> 5;
    const int lane = tid & 31;
    const int wr = (wid >> 1) * 32;     // warp row offset (0/32/64/96)
    const int wc = (wid & 1) * 64;      // warp col offset (0/64)
    const int g = lane >> 2;            // 0..7
    const int q = lane & 3;             // 0..3
    const int r0 = blockIdx.x * 128;

    // ldmatrix per-lane geometry
    const int lrow = lane & 7;
    const int lm = lane >> 3;
    const int arow0 = wr + (lm & 1) * 8 + lrow;    // A base row for this lane
    const int asel = lm >> 1;                      // A k-chunk select 0/1
    const int brow0 = wc + (lm >> 1) * 8 + lrow;   // B base row (code)
    const int bsel = lm & 1;                       // B k-chunk select 0/1
    const uint32_t abase = (uint32_t)(arow0 * 64);
    const int axorq = (arow0 >> 1) & 3;            // same for all mt (+16 rows)
    const uint32_t bbase = (uint32_t)(brow0 * 64);
    const int bxorq = (brow0 >> 1) & 3;            // same for all p

    float* sc2 = (float*)(smem + SC2_OFF);
    for (int c = tid; c < NB; c += 256) sc2[c] = g_c2[c];

    float acc[2][8][4];
    float bd[4][3]; int bi[4][3];
    #pragma unroll
    for (int s = 0; s < 4; s++)
        #pragma unroll
        for (int j = 0; j < 3; j++) { bd[s][j] = FLT_MAX; bi[s][j] = 0; }

    #pragma unroll
    for (int pi = 0; pi < 4; pi++) {
        load_tiles(sb, r0, pi);
        asm volatile("cp.async.commit_group;" ::: "memory");
    }

    for (int i = 0; i < 256; i++) {
        const int kt = i & 15;
        const int cc = i >> 4;

        if (i < 252) asm volatile("cp.async.wait_group 3;" ::: "memory");
        else         asm volatile("cp.async.wait_group 0;" ::: "memory");
        __syncthreads();
        if (i + 4 < 256) {
            load_tiles(sb, r0, i + 4);
            asm volatile("cp.async.commit_group;" ::: "memory");
        }

        if (kt == 0) {
            #pragma unroll
            for (int mt = 0; mt < 2; mt++)
                #pragma unroll
                for (int nt = 0; nt < 8; nt++)
                    #pragma unroll
                    for (int r = 0; r < 4; r++) acc[mt][nt][r] = 0.f;
        }

        const uint32_t stage = sb + STAGE0 + (uint32_t)(i % N_STAGE) * STAGE_SZ;
        #pragma unroll
        for (int ks = 0; ks < 2; ks++) {
            const uint32_t aoff = abase + (uint32_t)((((ks << 1) + asel) ^ axorq) << 4);
            const uint32_t boff = bbase + (uint32_t)((((ks << 1) + bsel) ^ bxorq) << 4);
            uint32_t a[2][4];
            ldsm_x4(a[0], stage + aoff);
            ldsm_x4(a[1], stage + aoff + 1024);   // +16 rows
            #pragma unroll
            for (int p = 0; p < 4; p++) {
                uint32_t b[4];
                ldsm_x4(b, stage + OFF_B + boff + p * 1024);
                #pragma unroll
                for (int mt = 0; mt < 2; mt++) {
                    mma16816(acc[mt][2 * p],     a[mt], b[0], b[1]);
                    mma16816(acc[mt][2 * p + 1], a[mt], b[2], b[3]);
                }
            }
        }

        if (kt == 15) {
            // chunk epilogue: d = c2 - 2*dot; track top-3 per row slot
            #pragma unroll
            for (int mt = 0; mt < 2; mt++) {
                #pragma unroll
                for (int nt = 0; nt < 8; nt++) {
                    int code0 = (cc << 7) + wc + nt * 8 + q * 2;
                    float c2a = sc2[code0], c2b = sc2[code0 + 1];
                    ins3(bd[mt*2],   bi[mt*2],   c2a - 2.f * acc[mt][nt][0], code0);
                    ins3(bd[mt*2],   bi[mt*2],   c2b - 2.f * acc[mt][nt][1], code0 + 1);
                    ins3(bd[mt*2+1], bi[mt*2+1], c2a - 2.f * acc[mt][nt][2], code0);
                    ins3(bd[mt*2+1], bi[mt*2+1], c2b - 2.f * acc[mt][nt][3], code0 + 1);
                }
            }
        }
    }

    // reduce across the 4 lanes sharing each row (xor 1, 2)
    #pragma unroll
    for (int s = 0; s < 4; s++) {
        #pragma unroll
        for (int o = 1; o <= 2; o <<= 1) {
            float od[3]; int oi[3];
            #pragma unroll
            for (int j = 0; j < 3; j++) {
                od[j] = __shfl_xor_sync(0xffffffffu, bd[s][j], o);
                oi[j] = __shfl_xor_sync(0xffffffffu, bi[s][j], o);
            }
            #pragma unroll
            for (int j = 0; j < 3; j++) ins3(bd[s], bi[s], od[j], oi[j]);
        }
    }

    // cross column-half merge via smem (overlays stage area; loop is done)
    float* md = (float*)(smem + SM_MD);   // [3][128]
    int*   mi = (int*)  (smem + SM_MI);   // [3][128]
    __syncthreads();
    if ((wid & 1) == 1 && q == 0) {
        #pragma unroll
        for (int s = 0; s < 4; s++) {
            int row = wr + (s >> 1) * 16 + (s & 1) * 8 + g;
            #pragma unroll
            for (int j = 0; j < 3; j++) { md[j * 128 + row] = bd[s][j]; mi[j * 128 + row] = bi[s][j]; }
        }
    }
    __syncthreads();
    if ((wid & 1) == 0 && q == 0) {
        #pragma unroll
        for (int s = 0; s < 4; s++) {
            int row = wr + (s >> 1) * 16 + (s & 1) * 8 + g;
            #pragma unroll
            for (int j = 0; j < 3; j++)
                ins3(bd[s], bi[s], md[j * 128 + row], mi[j * 128 + row]);
            g_idx[r0 + row] = bi[s][0];
            if (bd[s][1] - bd[s][0] < THRESH) {
                int pos = atomicAdd(&g_resc_cnt, 1);
                g_resc_row[pos] = r0 + row;
                g_resc_i1[pos]  = bi[s][0];
                g_resc_i2[pos]  = bi[s][1];
                g_resc_i3[pos]  = bi[s][2];
            }
        }
    }
}

// ===========================================================================
// Exact fp32 rescore of top-3 candidates for small-margin rows
// ===========================================================================
__global__ __launch_bounds__(256) void rescue_kernel(const float* __restrict__ x,
                                                     const float* __restrict__ cb) {
    const int cnt = g_resc_cnt;
    const int wid = threadIdx.x >> 5;
    const int lane = threadIdx.x & 31;
    for (int j = blockIdx.x * 8 + wid; j < cnt; j += gridDim.x * 8) {
        int row = g_resc_row[j];
        int cand[3] = { g_resc_i1[j], g_resc_i2[j], g_resc_i3[j] };
        int n = row >> 10, t = row & 1023;
        const float* xr = x + (size_t)n * CTS + t;
        float s[3] = {0.f, 0.f, 0.f};
        #pragma unroll 4
        for (int c = lane; c < CC; c += 32) {
            float xv = xr[(size_t)c * TT];
            s[0] += xv * cb[(size_t)cand[0] * CC + c];
            s[1] += xv * cb[(size_t)cand[1] * CC + c];
            s[2] += xv * cb[(size_t)cand[2] * CC + c];
        }
        #pragma unroll
        for (int o = 16; o; o >>= 1) {
            s[0] += __shfl_xor_sync(0xffffffffu, s[0], o);
            s[1] += __shfl_xor_sync(0xffffffffu, s[1], o);
            s[2] += __shfl_xor_sync(0xffffffffu, s[2], o);
        }
        if (lane == 0) {
            float bestd = g_c2[cand[0]] - 2.f * s[0];
            int besti = cand[0];
            #pragma unroll
            for (int m = 1; m < 3; m++) {
                float dm = g_c2[cand[m]] - 2.f * s[m];
                if (dm < bestd || (dm == bestd && cand[m] < besti)) { bestd = dm; besti = cand[m]; }
            }
            g_idx[row] = besti;
        }
    }
}

// ===========================================================================
// Gather codebook rows -> x_d_out, segment sums, commit-loss
// ===========================================================================
__global__ __launch_bounds__(256) void scatter_kernel(const float* __restrict__ x,
                                                      const float* __restrict__ cb,
                                                      float* __restrict__ out) {
    __shared__ int   sidx[32];
    __shared__ float tile[32][33];
    __shared__ float red[8];

    const int b = blockIdx.x;
    const int n = b >> 5;
    const int t0 = (b & 31) * 32;
    const int tid = threadIdx.x;
    const int w = tid >> 5;
    const int lane = tid & 31;

    if (tid < 32) sidx[tid] = g_idx[n * TT + t0 + tid];
    __syncthreads();
    if (tid < 32) atomicAdd(&g_new_cnt[sidx[tid]], 1.0f);

    const int mycode = sidx[lane];

    float lsum = 0.f;
    for (int c0 = 0; c0 < CC; c0 += 32) {
        #pragma unroll
        for (int i = 0; i < 4; i++) {
            int t = w * 4 + i;
            tile[t][lane] = cb[(size_t)sidx[t] * CC + c0 + lane];
        }
        __syncthreads();
        float xs[4];
        #pragma unroll
        for (int i = 0; i < 4; i++) {
            int cr = w * 4 + i;
            int c = c0 + cr;
            size_t off = (size_t)n * CTS + (size_t)c * TT + t0 + lane;
            float xv = x[off];
            float v = tile[lane][cr];
            out[OUT_XD + off] = v;
            float dd = xv - v;
            lsum += dd * dd;
            xs[i] = xv;
        }
        float* dst = &g_new_sum[(size_t)mycode * CC + c0 + w * 4];
        asm volatile("red.global.v4.f32.add [%0], {%1,%2,%3,%4};"
                     :: "l"(dst), "f"(xs[0]), "f"(xs[1]), "f"(xs[2]), "f"(xs[3])
                     : "memory");
        __syncthreads();
    }

    #pragma unroll
    for (int o = 16; o; o >>= 1) lsum += __shfl_xor_sync(0xffffffffu, lsum, o);
    if (lane == 0) red[w] = lsum;
    __syncthreads();
    if (tid == 0) {
        float s = 0.f;
        #pragma unroll
        for (int i = 0; i < 8; i++) s += red[i];
        atomicAdd(&g_loss, (double)s);
    }
}

// ===========================================================================
// EMA updates, codebook reset, perplexity partials
// ===========================================================================
__global__ __launch_bounds__(128) void finalize_kernel(const float* __restrict__ x,
                                                       const float* __restrict__ code_sum,
                                                       const float* __restrict__ code_count,
                                                       float* __restrict__ out) {
    const int k = blockIdx.x;
    const int tid = threadIdx.x;
    float ncnt = g_new_cnt[k];
    float cnt_ema = MUF * code_count[k] + OMM * ncnt;
    bool usage = (cnt_ema >= 1.0f);
    float denom = fmaxf(cnt_ema, 1e-10f);

    for (int c = tid; c < CC; c += 128) {
        float sema = MUF * code_sum[(size_t)k * CC + c] + OMM * g_new_sum[(size_t)k * CC + c];
        out[OUT_SEMA + (size_t)k * CC + c] = sema;
        float v;
        if (usage) v = sema / denom;
        else       v = x[(size_t)(k >> 10) * CTS + (size_t)c * TT + (k & 1023)];
        out[OUT_CB + (size_t)k * CC + c] = v;
    }
    if (tid == 0) {
        out[OUT_CEMA + k] = cnt_ema;
        float p = ncnt / 32768.0f;
        atomicAdd(&g_plx, p * logf(p + 1e-7f));
    }
}

__global__ void scalars_kernel(float* __restrict__ out) {
    out[OUT_LOSS] = (float)(g_loss * (1.0 / 16777216.0));
    out[OUT_PLX] = expf(-g_plx);
}

// ===========================================================================
extern "C" void kernel_launch(void* const* d_in, const int* in_sizes, int n_in,
                              void* d_out, int out_size) {
    const float* x    = (const float*)d_in[0];
    const float* cb   = (const float*)d_in[1];
    const float* csum = (const float*)d_in[2];
    const float* ccnt = (const float*)d_in[3];
    float* out = (float*)d_out;

    cudaFuncSetAttribute(mma_argmin_kernel,
                         cudaFuncAttributeMaxDynamicSharedMemorySize, SMEM_TOTAL_MMA);

    prep_cb<<<NB, 128>>>(cb);
    cvtx_kernel<<<NN * 512, 256>>>(x);
    mma_argmin_kernel<<<NT / 128, 256, SMEM_TOTAL_MMA>>>();
    rescue_kernel<<<128, 256>>>(x, cb);
    scatter_kernel<<<NN * (TT / 32), 256>>>(x, cb, out);
    finalize_kernel<<<NB, 128>>>(x, csum, ccnt, out);
    scalars_kernel<<<1, 1>>>(out);
}